// round 17
// baseline (speedup 1.0000x reference)
#include <cuda_runtime.h>
#include <cuda_bf16.h>
#include <math.h>
#include <stdint.h>

// ---------------- problem dims ------------------------------------------------
#define NB 1024
#define NT 64
#define ND 256
#define NL 256
#define NH 1024
#define EPSV 1e-7f
#define LOG2PI 1.8378770664093453f
#define BETAV (1.0f/3.0f)

typedef __nv_bfloat16 bf16;

// ---------------- scratch (device globals) ------------------------------------
__device__ __align__(16) bf16  g_y1[(size_t)NB * NT * NH];
__device__ __align__(16) bf16  g_ctx[(size_t)NB * NT * 512];
__device__ __align__(16) bf16  g_xst[(size_t)NB * NT * ND];
__device__ __align__(16) bf16  g_zs[(size_t)NB * NT * NL];
__device__ __align__(16) float g_z[NB * NL];
__device__ __align__(16) bf16  g_hf[NB * NH];
__device__ __align__(16) bf16  g_hh[NB * NH];
__device__ __align__(16) float g_q[NB * 512];
__device__ __align__(16) bf16  g_fctx[(size_t)NT * NB * NH];   // [t][b][1024] bf16
__device__ __align__(16) bf16  g_wtb[2424832];
__device__ __align__(16) float g_pb[64 * 8192];                // phase-B k-split partials
__device__ float g_dkl8[8 * NB];
__device__ float g_kl0[NB];
__device__ float g_partials[4096];
__device__ unsigned g_flagA[NT * 8];
__device__ unsigned g_flagB[NT * 8];   // slots 504..511 = z0-done
__device__ unsigned g_flagP[NT * 64];  // per-(t, tile) partial-done

// weight offsets in g_wtb (elements), stored transposed [N][K]
#define W_ENC1 0
#define W_ENC2 262144
#define W_QZ0  524288
#define W_F1Z  786432
#define W_F1C  1048576
#define W_F2   1572864
#define W_H1   1835008
#define W_H2   2097152
#define W_PROJ 2359296

// ---------------- helpers -----------------------------------------------------
__device__ __forceinline__ uint32_t s2u(const void* p) {
    uint32_t a;
    asm("{ .reg .u64 t; cvta.to.shared.u64 t, %1; cvt.u32.u64 %0, t; }" : "=r"(a) : "l"(p));
    return a;
}
__device__ __forceinline__ void cp16(uint32_t saddr, const void* g) {
    asm volatile("cp.async.cg.shared.global [%0], [%1], 16;" :: "r"(saddr), "l"(g));
}
__device__ __forceinline__ void ldsm4(uint32_t& r0, uint32_t& r1, uint32_t& r2, uint32_t& r3,
                                      uint32_t addr) {
    asm volatile("ldmatrix.sync.aligned.m8n8.x4.shared.b16 {%0,%1,%2,%3}, [%4];"
                 : "=r"(r0), "=r"(r1), "=r"(r2), "=r"(r3) : "r"(addr));
}
__device__ __forceinline__ void mma_bf16(float* c, uint32_t a0, uint32_t a1, uint32_t a2, uint32_t a3,
                                         uint32_t b0, uint32_t b1) {
    asm volatile("mma.sync.aligned.m16n8k16.row.col.f32.bf16.bf16.f32 "
                 "{%0,%1,%2,%3},{%4,%5,%6,%7},{%8,%9},{%0,%1,%2,%3};"
                 : "+f"(c[0]), "+f"(c[1]), "+f"(c[2]), "+f"(c[3])
                 : "r"(a0), "r"(a1), "r"(a2), "r"(a3), "r"(b0), "r"(b1));
}
__device__ __forceinline__ float block_reduce_sum_256(float v, float* sh) {
    int tid = threadIdx.x;
    sh[tid] = v;
    __syncthreads();
    #pragma unroll
    for (int s = 128; s > 0; s >>= 1) {
        if (tid < s) sh[tid] += sh[tid + s];
        __syncthreads();
    }
    float r = sh[0];
    __syncthreads();
    return r;
}
__device__ __forceinline__ void wait_flag(unsigned* f, unsigned tgt) {
    if (threadIdx.x == 0) {
        unsigned v;
        do {
            asm volatile("ld.acquire.gpu.u32 %0, [%1];" : "=r"(v) : "l"(f) : "memory");
        } while (v < tgt);
    }
    __syncthreads();
}
__device__ __forceinline__ void arrive_flag(unsigned* f) {
    __syncthreads();
    if (threadIdx.x == 0)
        asm volatile("red.release.gpu.add.u32 [%0], 1;" :: "l"(f) : "memory");
}

// ldmatrix lane-offset builders (stride 72 bf16 rows, bytes)
__device__ __forceinline__ uint32_t laneA_off(int lane) {
    return (uint32_t)((((lane & 15) * 72) + (((lane >> 4) & 1) << 3)) << 1);
}
__device__ __forceinline__ uint32_t laneB_off(int lane) {
    int g = lane >> 3;
    return (uint32_t)(((((lane & 7) + ((g >> 1) << 3)) * 72) + ((g & 1) << 3)) << 1);
}

// ---------------- standalone bf16 GEMM ----------------------------------------
struct GArgs {
    const bf16* A; int lda;
    const bf16* W;
    const float* bias;
    void* C; int ldc;
    int K;
};

template<int BMT, int ACT, int OUTBF, int EPI, int TSCAT>
__global__ void __launch_bounds__(256, 2)
gemm_bf(GArgs g0, GArgs g1, int mSplit,
        const float* __restrict__ xs, const float* __restrict__ nstd_p,
        float* __restrict__ partials)
{
    extern __shared__ char smem[];
    constexpr int MT  = (BMT + 31) / 32;
    constexpr int ASZ = BMT * 72;
    constexpr int BSZ = 128 * 72;
    constexpr int STG = ASZ + BSZ;

    const int tid  = threadIdx.x;
    const int wid  = tid >> 5;
    const int lane = tid & 31;
    const int lr   = lane >> 2;
    const int lc   = lane & 3;

    const bool grp1 = ((int)blockIdx.y >= mSplit);
    const GArgs g = grp1 ? g1 : g0;
    const int bm = (grp1 ? ((int)blockIdx.y - mSplit) : (int)blockIdx.y) * BMT;
    const int bn = (int)blockIdx.x * 128;

    const uint32_t sbase = s2u(smem);
    const int warpM = (wid >> 2) * (BMT / 2);
    const int warpN = (wid & 3) * 32;
    const uint32_t lA = laneA_off(lane);
    const uint32_t lB = laneB_off(lane);

    auto loadtile = [&](int s, int c) {
        const int k0 = c << 6;
        uint32_t sA = sbase + (uint32_t)(s * STG) * 2u;
        uint32_t sB = sA + (uint32_t)ASZ * 2u;
        const bf16* Ag = g.A + (size_t)bm * g.lda + k0;
        #pragma unroll
        for (int i = 0; i < BMT / 32; i++) {
            int idx = tid + (i << 8);
            int m = idx >> 3, k8 = (idx & 7) << 3;
            cp16(sA + (uint32_t)(m * 72 + k8) * 2u, Ag + (size_t)m * g.lda + k8);
        }
        const bf16* Wg = g.W + (size_t)bn * g.K + k0;
        #pragma unroll
        for (int i = 0; i < 4; i++) {
            int idx = tid + (i << 8);
            int n = idx >> 3, k8 = (idx & 7) << 3;
            cp16(sB + (uint32_t)(n * 72 + k8) * 2u, Wg + (size_t)n * g.K + k8);
        }
        asm volatile("cp.async.commit_group;" ::: "memory");
    };

    float acc[MT][4][4];
    #pragma unroll
    for (int mt = 0; mt < MT; mt++)
        #pragma unroll
        for (int nt = 0; nt < 4; nt++)
            #pragma unroll
            for (int r = 0; r < 4; r++) acc[mt][nt][r] = 0.f;

    const int nch = g.K >> 6;
    loadtile(0, 0);
    if (nch > 1) loadtile(1, 1);

    for (int c = 0; c < nch; c++) {
        if (c + 1 < nch) asm volatile("cp.async.wait_group 1;" ::: "memory");
        else             asm volatile("cp.async.wait_group 0;" ::: "memory");
        __syncthreads();
        const uint32_t stg = sbase + (uint32_t)((c & 1) * STG) * 2u;
        const uint32_t aB = stg + (uint32_t)(warpM * 144) + lA;
        const uint32_t bB = stg + (uint32_t)ASZ * 2u + (uint32_t)(warpN * 144) + lB;
        #pragma unroll
        for (int ks = 0; ks < 4; ks++) {
            uint32_t b0[4], b1[4];
            ldsm4(b0[0], b1[0], b0[1], b1[1], bB + ks * 32);
            ldsm4(b0[2], b1[2], b0[3], b1[3], bB + 16 * 144 + ks * 32);
            #pragma unroll
            for (int mt = 0; mt < MT; mt++) {
                uint32_t a0, a1, a2, a3;
                ldsm4(a0, a1, a2, a3, aB + (uint32_t)(mt * 16 * 144) + ks * 32);
                #pragma unroll
                for (int nt = 0; nt < 4; nt++)
                    mma_bf16(acc[mt][nt], a0, a1, a2, a3, b0[nt], b1[nt]);
            }
        }
        __syncthreads();
        if (c + 2 < nch) loadtile(c & 1, c + 2);
    }

    float loc = 0.f;
    const float invs = EPI ? (1.f / nstd_p[0]) : 0.f;
    #pragma unroll
    for (int mt = 0; mt < MT; mt++) {
        const int row0 = bm + warpM + mt * 16 + lr;
        #pragma unroll
        for (int nt = 0; nt < 4; nt++) {
            const int col = bn + warpN + nt * 8 + (lc << 1);
            float2 bb = *reinterpret_cast<const float2*>(g.bias + col);
            float v00 = acc[mt][nt][0] + bb.x;
            float v01 = acc[mt][nt][1] + bb.y;
            float v10 = acc[mt][nt][2] + bb.x;
            float v11 = acc[mt][nt][3] + bb.y;
            if (ACT) { v00 = tanhf(v00); v01 = tanhf(v01); v10 = tanhf(v10); v11 = tanhf(v11); }
            if (EPI) {
                float2 x0 = *reinterpret_cast<const float2*>(xs + (size_t)row0 * g.ldc + col);
                float2 x1 = *reinterpret_cast<const float2*>(xs + (size_t)(row0 + 8) * g.ldc + col);
                float r0 = (x0.x - v00) * invs, r1 = (x0.y - v01) * invs;
                float r2 = (x1.x - v10) * invs, r3 = (x1.y - v11) * invs;
                loc += r0 * r0 + r1 * r1 + r2 * r2 + r3 * r3;
            } else if (TSCAT) {
                bf16* Cb = (bf16*)g.C;
                size_t o0 = ((size_t)(row0 & 63) * NB + (row0 >> 6)) * NH + col;
                int row1 = row0 + 8;
                size_t o1 = ((size_t)(row1 & 63) * NB + (row1 >> 6)) * NH + col;
                *reinterpret_cast<__nv_bfloat162*>(Cb + o0) = __floats2bfloat162_rn(v00, v01);
                *reinterpret_cast<__nv_bfloat162*>(Cb + o1) = __floats2bfloat162_rn(v10, v11);
            } else if (OUTBF) {
                bf16* Cb = (bf16*)g.C;
                *reinterpret_cast<__nv_bfloat162*>(Cb + (size_t)row0 * g.ldc + col) = __floats2bfloat162_rn(v00, v01);
                *reinterpret_cast<__nv_bfloat162*>(Cb + (size_t)(row0 + 8) * g.ldc + col) = __floats2bfloat162_rn(v10, v11);
            } else {
                float* Cf = (float*)g.C;
                *reinterpret_cast<float2*>(Cf + (size_t)row0 * g.ldc + col) = make_float2(v00, v01);
                *reinterpret_cast<float2*>(Cf + (size_t)(row0 + 8) * g.ldc + col) = make_float2(v10, v11);
            }
        }
    }
    if (EPI) {
        __syncthreads();
        float tot = block_reduce_sum_256(loc, (float*)smem);
        if (tid == 0) partials[blockIdx.y * gridDim.x + blockIdx.x] = -0.5f * tot;
    }
}

// ---------------- fused prologue ------------------------------------------------
struct PrepArgs {
    const float* src[9];
    int off[9];
    int K[9], N[9];
    int tileOff[10];
    const float* xs;
};

__global__ void __launch_bounds__(256)
prep_k(PrepArgs pa, bf16* __restrict__ wtb, bf16* __restrict__ ctx, bf16* __restrict__ xst,
       float* __restrict__ dkl8, unsigned* __restrict__ flagA, unsigned* __restrict__ flagB,
       unsigned* __restrict__ flagP)
{
    __shared__ float t[32][33];
    const int bx = blockIdx.x;
    const int tid = threadIdx.x;

    if (bx == 0) {
        #pragma unroll
        for (int i = 0; i < 32; i++) dkl8[tid + i * 256] = 0.f;
        #pragma unroll
        for (int i = 0; i < 2; i++) {
            flagA[tid + i * 256] = 0u;
            flagB[tid + i * 256] = 0u;
        }
        #pragma unroll
        for (int i = 0; i < 16; i++) {
            int idx = tid + i * 256;
            if (idx < NT * 64) flagP[idx] = 0u;
        }
    }

    if (bx < pa.tileOff[9]) {
        int m = 0;
        #pragma unroll
        for (int i = 1; i < 9; i++) if (bx >= pa.tileOff[i]) m = i;
        const int local = bx - pa.tileOff[m];
        const int K = pa.K[m], N = pa.N[m];
        const int nTiles = N >> 5;
        const int n0 = (local % nTiles) << 5;
        const int k0 = (local / nTiles) << 5;
        const float* W = pa.src[m];
        bf16* Wt = wtb + pa.off[m];
        const int tx = tid & 31, ty = tid >> 5;
        #pragma unroll
        for (int j = 0; j < 4; j++)
            t[ty + j * 8][tx] = W[(size_t)(k0 + ty + j * 8) * N + n0 + tx];
        __syncthreads();
        #pragma unroll
        for (int j = 0; j < 4; j++)
            Wt[(size_t)(n0 + ty + j * 8) * K + k0 + tx] = __float2bfloat16(t[tx][ty + j * 8]);
    } else {
        size_t i0 = ((size_t)(bx - pa.tileOff[9]) << 10) + ((size_t)tid << 2);
        float4 v = *reinterpret_cast<const float4*>(pa.xs + i0);
        float vv[4] = {v.x, v.y, v.z, v.w};
        #pragma unroll
        for (int u = 0; u < 4; u++) {
            size_t idx = i0 + u;
            size_t bt = idx >> 8, d = idx & 255;
            bf16 b = __float2bfloat16(vv[u]);
            ctx[bt * 512 + 256 + d] = b;
            xst[idx] = b;
        }
    }
}

// ---------------- persistent scan ---------------------------------------------
__device__ void gemmA(const bf16* A, const bf16* W, bf16* C,
                      const bf16* fadd, const float* bias,
                      int bm, int bn, char* smem)
{
    constexpr int lda = NT * NL;
    constexpr int ASZ = 128 * 72, STG = 2 * 128 * 72;
    const int tid = threadIdx.x;
    const int wid = tid >> 5, lane = tid & 31;
    const int lr = lane >> 2, lc = lane & 3;
    const uint32_t sbase = s2u(smem);
    const int warpM = (wid >> 2) * 64;
    const int warpN = (wid & 3) * 32;
    const uint32_t lA = laneA_off(lane);
    const uint32_t lB = laneB_off(lane);

    auto loadtile = [&](int s, int c) {
        const int k0 = c << 6;
        uint32_t sA = sbase + (uint32_t)(s * STG) * 2u;
        uint32_t sB = sA + (uint32_t)ASZ * 2u;
        #pragma unroll
        for (int i = 0; i < 4; i++) {
            int idx = tid + (i << 8);
            int m = idx >> 3, k8 = (idx & 7) << 3;
            cp16(sA + (uint32_t)(m * 72 + k8) * 2u, A + (size_t)(bm + m) * lda + k0 + k8);
        }
        #pragma unroll
        for (int i = 0; i < 4; i++) {
            int idx = tid + (i << 8);
            int n = idx >> 3, k8 = (idx & 7) << 3;
            cp16(sB + (uint32_t)(n * 72 + k8) * 2u, W + (size_t)(bn + n) * 256 + k0 + k8);
        }
        asm volatile("cp.async.commit_group;" ::: "memory");
    };

    float acc[4][4][4];
    #pragma unroll
    for (int mt = 0; mt < 4; mt++)
        #pragma unroll
        for (int nt = 0; nt < 4; nt++)
            #pragma unroll
            for (int r = 0; r < 4; r++) acc[mt][nt][r] = 0.f;

    loadtile(0, 0);
    loadtile(1, 1);
    loadtile(2, 2);
    for (int c = 0; c < 4; c++) {
        if (c <= 1)      asm volatile("cp.async.wait_group 2;" ::: "memory");
        else if (c == 2) asm volatile("cp.async.wait_group 1;" ::: "memory");
        else             asm volatile("cp.async.wait_group 0;" ::: "memory");
        __syncthreads();
        if (c + 3 < 4) loadtile(c + 3, c + 3);

        const uint32_t stg = sbase + (uint32_t)(c * STG) * 2u;
        const uint32_t aB = stg + (uint32_t)(warpM * 144) + lA;
        const uint32_t bB = stg + (uint32_t)ASZ * 2u + (uint32_t)(warpN * 144) + lB;
        #pragma unroll
        for (int ks = 0; ks < 4; ks++) {
            uint32_t b0[4], b1[4];
            ldsm4(b0[0], b1[0], b0[1], b1[1], bB + ks * 32);
            ldsm4(b0[2], b1[2], b0[3], b1[3], bB + 16 * 144 + ks * 32);
            #pragma unroll
            for (int mt = 0; mt < 4; mt++) {
                uint32_t a0, a1, a2, a3;
                ldsm4(a0, a1, a2, a3, aB + (uint32_t)(mt * 16 * 144) + ks * 32);
                #pragma unroll
                for (int nt = 0; nt < 4; nt++)
                    mma_bf16(acc[mt][nt], a0, a1, a2, a3, b0[nt], b1[nt]);
            }
        }
    }

    #pragma unroll
    for (int mt = 0; mt < 4; mt++) {
        const int row0 = bm + warpM + mt * 16 + lr;
        #pragma unroll
        for (int nt = 0; nt < 4; nt++) {
            const int gcol = bn + warpN + nt * 8 + (lc << 1);
            float a00, a01, a10, a11;
            if (fadd) {
                __nv_bfloat162 f0 = *reinterpret_cast<const __nv_bfloat162*>(fadd + (size_t)row0 * NH + gcol);
                __nv_bfloat162 f1 = *reinterpret_cast<const __nv_bfloat162*>(fadd + (size_t)(row0 + 8) * NH + gcol);
                a00 = __low2float(f0); a01 = __high2float(f0);
                a10 = __low2float(f1); a11 = __high2float(f1);
            } else {
                float2 bb = *reinterpret_cast<const float2*>(bias + gcol);
                a00 = bb.x; a01 = bb.y; a10 = bb.x; a11 = bb.y;
            }
            float v00 = tanhf(acc[mt][nt][0] + a00);
            float v01 = tanhf(acc[mt][nt][1] + a01);
            float v10 = tanhf(acc[mt][nt][2] + a10);
            float v11 = tanhf(acc[mt][nt][3] + a11);
            *reinterpret_cast<__nv_bfloat162*>(C + (size_t)row0 * NH + gcol) = __floats2bfloat162_rn(v00, v01);
            *reinterpret_cast<__nv_bfloat162*>(C + (size_t)(row0 + 8) * NH + gcol) = __floats2bfloat162_rn(v10, v11);
        }
    }
}

#define SMEMP 147456

__global__ void __launch_bounds__(256)
scan_k(const float* __restrict__ ts, const float* __restrict__ noise,
       float* __restrict__ z, bf16* __restrict__ zs,
       bf16* __restrict__ hf, bf16* __restrict__ hh,
       const bf16* __restrict__ wf1z, const bf16* __restrict__ wh1,
       const bf16* __restrict__ wf2, const bf16* __restrict__ wh2,
       const float* __restrict__ hb1,
       const float* __restrict__ fb2, const float* __restrict__ hb2,
       const bf16* __restrict__ fctx,
       const float* __restrict__ gamma, float* __restrict__ dkl8,
       unsigned* flagA, unsigned* flagB, unsigned* flagP,
       float* __restrict__ pb,
       const float* __restrict__ q, const float* __restrict__ eps0,
       const float* __restrict__ pm, const float* __restrict__ pl,
       float* __restrict__ kl0)
{
    extern __shared__ char smem[];
    const int tid = threadIdx.x;
    const int cta = blockIdx.x;
    const int wid = tid >> 5, lane = tid & 31;
    const int lr = lane >> 2, lc = lane & 3;

    // ---- fused z0 prologue ----
    {
        const int b = cta * 8 + wid;
        float part = 0.f;
        #pragma unroll
        for (int j = 0; j < 8; j++) {
            const int l = lane + j * 32;
            float qm = q[b * 512 + l];
            float ql = q[b * 512 + 256 + l];
            float z0 = qm + expf(ql) * eps0[b * NL + l];
            z[b * NL + l] = z0;
            zs[(size_t)b * NT * NL + l] = __float2bfloat16(z0);
            float pmv = pm[l], plv = pl[l];
            float dm = qm - pmv;
            part += plv - ql + (expf(2.f * ql) + dm * dm) / (2.f * expf(2.f * plv)) - 0.5f;
        }
        #pragma unroll
        for (int s = 16; s > 0; s >>= 1) part += __shfl_xor_sync(0xffffffff, part, s);
        if (lane == 0) kl0[b] = part;
    }
    arrive_flag(&flagB[504 + (cta >> 4)]);

    // phase A tile: 8 bm-groups x 16 bn-groups
    const int a_bm = (cta >> 4) * 128;
    const int a_bnI = cta & 15;
    const int a_grp = a_bm >> 7;

    // phase B: 64 tiles of 128x32 (8 m-groups x 8 n-groups), K split over CTA pairs
    const int b_tile = cta >> 1;
    const int b_kg   = cta & 1;
    const int b_mg   = b_tile >> 3;
    const int b_ng   = b_tile & 7;
    const int b_bm   = b_mg * 128;
    const int b_bn   = b_ng * 32;
    const int b_grp  = b_mg;
    const int kbase  = b_kg << 9;

    // phase B smem: Af[128x72] Ah[128x72] Bf[32x72] Bh[32x72], 3 stages
    constexpr int AF = 0, AH = 128 * 72, BF = 256 * 72, BH = 288 * 72;
    constexpr int STG2 = 320 * 72;         // 46080 B/stage, 3 stages = 138240 <= SMEMP
    const uint32_t sbase = s2u(smem);
    const uint32_t lA = laneA_off(lane);
    const uint32_t lB = laneB_off(lane);

    for (int t = 0; t < NT - 1; t++) {
        // ---------------- phase A ----------------
        wait_flag(&flagB[(t == 0) ? (504 + a_grp) : ((t - 1) * 8 + a_grp)], 16);

        const bf16* Az = zs + (size_t)t * NL;
        if (a_bnI < 8)
            gemmA(Az, wf1z, hf, fctx + (size_t)(t + 1) * NB * NH, nullptr,
                  a_bm, a_bnI * 128, smem);
        else
            gemmA(Az, wh1, hh, nullptr, hb1, a_bm, (a_bnI - 8) * 128, smem);

        arrive_flag(&flagA[t * 8 + a_grp]);

        // ---------------- phase B ----------------
        wait_flag(&flagA[t * 8 + b_grp], 16);

        auto loadB = [&](int s, int c) {
            const int k0 = kbase + (c << 6);
            uint32_t base = sbase + (uint32_t)(s * STG2) * 2u;
            #pragma unroll
            for (int i = 0; i < 4; i++) {
                int idx = tid + (i << 8);
                int m = idx >> 3, k8 = (idx & 7) << 3;
                cp16(base + (uint32_t)(AF + m * 72 + k8) * 2u, hf + (size_t)(b_bm + m) * NH + k0 + k8);
                cp16(base + (uint32_t)(AH + m * 72 + k8) * 2u, hh + (size_t)(b_bm + m) * NH + k0 + k8);
            }
            {
                int n = tid >> 3, k8 = (tid & 7) << 3;
                cp16(base + (uint32_t)(BF + n * 72 + k8) * 2u, wf2 + (size_t)(b_bn + n) * NH + k0 + k8);
                cp16(base + (uint32_t)(BH + n * 72 + k8) * 2u, wh2 + (size_t)(b_bn + n) * NH + k0 + k8);
            }
            asm volatile("cp.async.commit_group;" ::: "memory");
        };

        float fd[2][2][4], hd[2][2][4];
        #pragma unroll
        for (int mt = 0; mt < 2; mt++)
            #pragma unroll
            for (int nt = 0; nt < 2; nt++)
                #pragma unroll
                for (int r = 0; r < 4; r++) { fd[mt][nt][r] = 0.f; hd[mt][nt][r] = 0.f; }

        const int warpM = (wid & 3) << 5;      // 0,32,64,96
        const int warpNl = (wid >> 2) << 4;    // 0,16
        loadB(0, 0);
        loadB(1, 1);
        for (int c = 0; c < 8; c++) {
            if (c < 7) asm volatile("cp.async.wait_group 1;" ::: "memory");
            else       asm volatile("cp.async.wait_group 0;" ::: "memory");
            __syncthreads();
            if (c + 2 < 8) loadB((c + 2) % 3, c + 2);

            const uint32_t stb = sbase + (uint32_t)((c % 3) * STG2) * 2u;
            const uint32_t afB = stb + (uint32_t)(warpM * 144) + lA;
            const uint32_t ahB = stb + (uint32_t)(AH * 2 + warpM * 144) + lA;
            const uint32_t bfB = stb + (uint32_t)(BF * 2 + warpNl * 144) + lB;
            const uint32_t bhB = stb + (uint32_t)(BH * 2 + warpNl * 144) + lB;
            #pragma unroll
            for (int ks = 0; ks < 4; ks++) {
                uint32_t fb0_[2], fb1_[2], hb0_[2], hb1_[2];
                ldsm4(fb0_[0], fb1_[0], fb0_[1], fb1_[1], bfB + ks * 32);
                ldsm4(hb0_[0], hb1_[0], hb0_[1], hb1_[1], bhB + ks * 32);
                #pragma unroll
                for (int mt = 0; mt < 2; mt++) {
                    uint32_t fa0, fa1, fa2, fa3, ha0, ha1, ha2, ha3;
                    ldsm4(fa0, fa1, fa2, fa3, afB + (uint32_t)(mt * 16 * 144) + ks * 32);
                    ldsm4(ha0, ha1, ha2, ha3, ahB + (uint32_t)(mt * 16 * 144) + ks * 32);
                    #pragma unroll
                    for (int nt = 0; nt < 2; nt++) {
                        mma_bf16(fd[mt][nt], fa0, fa1, fa2, fa3, fb0_[nt], fb1_[nt]);
                        mma_bf16(hd[mt][nt], ha0, ha1, ha2, ha3, hb0_[nt], hb1_[nt]);
                    }
                }
            }
        }

        float* pbt = pb + (size_t)b_tile * 8192 + tid * 32;
        if (b_kg == 1) {
            // ---- store partials, signal, done ----
            #pragma unroll
            for (int mt = 0; mt < 2; mt++)
                #pragma unroll
                for (int nt = 0; nt < 2; nt++) {
                    *reinterpret_cast<float4*>(pbt + (mt * 2 + nt) * 4) =
                        make_float4(fd[mt][nt][0], fd[mt][nt][1], fd[mt][nt][2], fd[mt][nt][3]);
                    *reinterpret_cast<float4*>(pbt + 16 + (mt * 2 + nt) * 4) =
                        make_float4(hd[mt][nt][0], hd[mt][nt][1], hd[mt][nt][2], hd[mt][nt][3]);
                }
            arrive_flag(&flagP[t * 64 + b_tile]);
            arrive_flag(&flagB[t * 8 + b_grp]);   // hf/hh reads done (WAR cover)
        } else {
            // ---- merge kg1 partials (fixed order: kg0 + kg1) ----
            wait_flag(&flagP[t * 64 + b_tile], 1);
            #pragma unroll
            for (int mt = 0; mt < 2; mt++)
                #pragma unroll
                for (int nt = 0; nt < 2; nt++) {
                    float4 pf = *reinterpret_cast<const float4*>(pbt + (mt * 2 + nt) * 4);
                    float4 ph = *reinterpret_cast<const float4*>(pbt + 16 + (mt * 2 + nt) * 4);
                    fd[mt][nt][0] += pf.x; fd[mt][nt][1] += pf.y;
                    fd[mt][nt][2] += pf.z; fd[mt][nt][3] += pf.w;
                    hd[mt][nt][0] += ph.x; hd[mt][nt][1] += ph.y;
                    hd[mt][nt][2] += ph.z; hd[mt][nt][3] += ph.w;
                }

            // ---- fused step update (128 rows x 32 cols) ----
            const float dt = ts[t + 1] - ts[t];
            const float sq = sqrtf(dt);
            float* sred = (float*)smem;     // 256 floats, stage-0 area (retired)
            float prm[2][2];
            #pragma unroll
            for (int mt = 0; mt < 2; mt++) { prm[mt][0] = 0.f; prm[mt][1] = 0.f; }

            #pragma unroll
            for (int mt = 0; mt < 2; mt++) {
                #pragma unroll
                for (int nt = 0; nt < 2; nt++) {
                    const int col = b_bn + warpNl + nt * 8 + (lc << 1);
                    const float fb0 = fb2[col], fb1v = fb2[col + 1];
                    const float hb0 = hb2[col], hb1v = hb2[col + 1];
                    float d00 = fd[mt][nt][0] + fb0, d01 = fd[mt][nt][1] + fb1v;
                    float d10 = fd[mt][nt][2] + fb0, d11 = fd[mt][nt][3] + fb1v;
                    float p00 = hd[mt][nt][0] + hb0, p01 = hd[mt][nt][1] + hb1v;
                    float p10 = hd[mt][nt][2] + hb0, p11 = hd[mt][nt][3] + hb1v;

                    const float df0 = sqrtf(2.f / (BETAV * gamma[col]));
                    const float df1 = sqrtf(2.f / (BETAV * gamma[col + 1]));
                    float den0 = fabsf(df0) > EPSV ? df0 : ((df0 > 0.f) - (df0 < 0.f)) * EPSV;
                    float den1 = fabsf(df1) > EPSV ? df1 : ((df1 > 0.f) - (df1 < 0.f)) * EPSV;
                    float r00 = (d00 - p00) / den0, r01 = (d01 - p01) / den1;
                    float r10 = (d10 - p10) / den0, r11 = (d11 - p11) / den1;
                    prm[mt][0] += r00 * r00 + r01 * r01;
                    prm[mt][1] += r10 * r10 + r11 * r11;

                    const int b0r = b_bm + warpM + mt * 16 + lr, b1r = b0r + 8;
                    {
                        size_t zi = (size_t)b0r * NL + col;
                        float e0 = noise[((size_t)t * NB + b0r) * NL + col];
                        float e1 = noise[((size_t)t * NB + b0r) * NL + col + 1];
                        float zn0 = z[zi] + d00 * dt + df0 * sq * e0;
                        float zn1 = z[zi + 1] + d01 * dt + df1 * sq * e1;
                        z[zi] = zn0; z[zi + 1] = zn1;
                        *reinterpret_cast<__nv_bfloat162*>(zs + ((size_t)b0r * NT + t + 1) * NL + col)
                            = __floats2bfloat162_rn(zn0, zn1);
                    }
                    {
                        size_t zi = (size_t)b1r * NL + col;
                        float e0 = noise[((size_t)t * NB + b1r) * NL + col];
                        float e1 = noise[((size_t)t * NB + b1r) * NL + col + 1];
                        float zn0 = z[zi] + d10 * dt + df0 * sq * e0;
                        float zn1 = z[zi + 1] + d11 * dt + df1 * sq * e1;
                        z[zi] = zn0; z[zi + 1] = zn1;
                        *reinterpret_cast<__nv_bfloat162*>(zs + ((size_t)b1r * NT + t + 1) * NL + col)
                            = __floats2bfloat162_rn(zn0, zn1);
                    }
                }
            }

            // rate reduction: shuffle over lc, stage to smem, accumulate dkl
            #pragma unroll
            for (int mt = 0; mt < 2; mt++) {
                prm[mt][0] += __shfl_xor_sync(0xffffffff, prm[mt][0], 1);
                prm[mt][0] += __shfl_xor_sync(0xffffffff, prm[mt][0], 2);
                prm[mt][1] += __shfl_xor_sync(0xffffffff, prm[mt][1], 1);
                prm[mt][1] += __shfl_xor_sync(0xffffffff, prm[mt][1], 2);
            }
            const int ngrp = wid >> 2;
            if (lc == 0) {
                #pragma unroll
                for (int mt = 0; mt < 2; mt++) {
                    sred[(warpM + mt * 16 + lr) * 2 + ngrp] = prm[mt][0];
                    sred[(warpM + mt * 16 + lr + 8) * 2 + ngrp] = prm[mt][1];
                }
            }
            __syncthreads();
            if (tid < 128)
                dkl8[b_ng * NB + b_bm + tid] += (sred[tid * 2] + sred[tid * 2 + 1]) * dt;

            arrive_flag(&flagB[t * 8 + b_grp]);
        }
    }
}

// ---------------- finalize -----------------------------------------------------
__global__ void finalize_k(const float* __restrict__ partials, int np,
                           const float* __restrict__ dkl8, const float* __restrict__ kl0,
                           const float* __restrict__ nstd_p, float* __restrict__ out)
{
    __shared__ float sh[256];
    int tid = threadIdx.x;
    float s = 0.f;
    for (int i = tid; i < np; i += 256) s += partials[i];
    float tot = block_reduce_sum_256(s, sh);

    float s2 = 0.f;
    for (int i = tid; i < 8 * NB; i += 256) s2 += dkl8[i];
    float dkl_tot = block_reduce_sum_256(s2, sh);

    float s3 = 0.f;
    for (int i = tid; i < NB; i += 256) s3 += kl0[i];
    float kl0_tot = block_reduce_sum_256(s3, sh);

    if (tid == 0) {
        float nstd = nstd_p[0];
        float cst = (float)NT * (float)ND * (-logf(nstd) - 0.5f * LOG2PI);
        float log_pxs = tot / (float)NB + cst;
        out[0] = -log_pxs;
        out[1] = dkl_tot / (float)NB + kl0_tot / (float)NB;
    }
}

// ---------------- launch ------------------------------------------------------
#define SMEM128 (2 * (128*72 + 128*72) * 2)   // 73728

extern "C" void kernel_launch(void* const* d_in, const int* in_sizes, int n_in,
                              void* d_out, int out_size)
{
    const float* xs        = (const float*)d_in[0];
    const float* ts        = (const float*)d_in[1];
    const float* noise_std = (const float*)d_in[2];
    const float* eps0      = (const float*)d_in[3];
    const float* noise     = (const float*)d_in[4];
    const float* enc_w1    = (const float*)d_in[5];
    const float* enc_b1    = (const float*)d_in[6];
    const float* enc_w2    = (const float*)d_in[7];
    const float* enc_b2    = (const float*)d_in[8];
    const float* qz0_w     = (const float*)d_in[9];
    const float* qz0_b     = (const float*)d_in[10];
    const float* f_w1      = (const float*)d_in[11];
    const float* f_b1      = (const float*)d_in[12];
    const float* f_w2      = (const float*)d_in[13];
    const float* f_b2      = (const float*)d_in[14];
    const float* h_w1      = (const float*)d_in[15];
    const float* h_b1      = (const float*)d_in[16];
    const float* h_w2      = (const float*)d_in[17];
    const float* h_b2      = (const float*)d_in[18];
    const float* proj_w    = (const float*)d_in[19];
    const float* proj_b    = (const float*)d_in[20];
    const float* pz0_mean  = (const float*)d_in[21];
    const float* pz0_logstd= (const float*)d_in[22];
    const float* gamma     = (const float*)d_in[23];

    bf16 *y1, *ctx, *xst, *zs, *hf, *hh, *wtb, *fctx;
    float *z, *q, *dkl8, *kl0, *partials, *pb;
    unsigned *flagA, *flagB, *flagP;
    cudaGetSymbolAddress((void**)&y1, g_y1);
    cudaGetSymbolAddress((void**)&ctx, g_ctx);
    cudaGetSymbolAddress((void**)&xst, g_xst);
    cudaGetSymbolAddress((void**)&zs, g_zs);
    cudaGetSymbolAddress((void**)&z, g_z);
    cudaGetSymbolAddress((void**)&hf, g_hf);
    cudaGetSymbolAddress((void**)&hh, g_hh);
    cudaGetSymbolAddress((void**)&q, g_q);
    cudaGetSymbolAddress((void**)&fctx, g_fctx);
    cudaGetSymbolAddress((void**)&wtb, g_wtb);
    cudaGetSymbolAddress((void**)&dkl8, g_dkl8);
    cudaGetSymbolAddress((void**)&kl0, g_kl0);
    cudaGetSymbolAddress((void**)&partials, g_partials);
    cudaGetSymbolAddress((void**)&pb, g_pb);
    cudaGetSymbolAddress((void**)&flagA, g_flagA);
    cudaGetSymbolAddress((void**)&flagB, g_flagB);
    cudaGetSymbolAddress((void**)&flagP, g_flagP);

    cudaFuncSetAttribute(gemm_bf<128,1,1,0,0>, cudaFuncAttributeMaxDynamicSharedMemorySize, SMEM128);
    cudaFuncSetAttribute(gemm_bf<128,0,1,0,0>, cudaFuncAttributeMaxDynamicSharedMemorySize, SMEM128);
    cudaFuncSetAttribute(gemm_bf<128,0,0,0,0>, cudaFuncAttributeMaxDynamicSharedMemorySize, SMEM128);
    cudaFuncSetAttribute(gemm_bf<128,0,0,1,0>, cudaFuncAttributeMaxDynamicSharedMemorySize, SMEM128);
    cudaFuncSetAttribute(gemm_bf<128,0,0,0,1>, cudaFuncAttributeMaxDynamicSharedMemorySize, SMEM128);
    cudaFuncSetAttribute(scan_k, cudaFuncAttributeMaxDynamicSharedMemorySize, SMEMP);

    const int M = NB * NT;

    // ---- launch 1: fused prep ----
    {
        PrepArgs pa{};
        const float* srcs[9] = {enc_w1, enc_w2, qz0_w, f_w1, f_w1 + 256 * NH,
                                f_w2, h_w1, h_w2, proj_w};
        int offs[9] = {W_ENC1, W_ENC2, W_QZ0, W_F1Z, W_F1C, W_F2, W_H1, W_H2, W_PROJ};
        int Ks[9]   = {256, 1024, 512, 256, 512, 1024, 256, 1024, 256};
        int Ns[9]   = {1024, 256, 512, 1024, 1024, 256, 1024, 256, 256};
        int off = 0;
        for (int i = 0; i < 9; i++) {
            pa.src[i] = srcs[i]; pa.off[i] = offs[i]; pa.K[i] = Ks[i]; pa.N[i] = Ns[i];
            pa.tileOff[i] = off;
            off += (Ns[i] >> 5) * (Ks[i] >> 5);
        }
        pa.tileOff[9] = off;
        pa.xs = xs;
        const int nCopy = (int)((size_t)M * ND / 1024);
        prep_k<<<off + nCopy, 256>>>(pa, wtb, ctx, xst, dkl8, flagA, flagB, flagP);
    }

    GArgs zg{};

    // ---- encoder ----
    {
        GArgs a{xst, ND, wtb + W_ENC1, enc_b1, y1, NH, ND};
        gemm_bf<128,1,1,0,0><<<dim3(NH/128, M/128), 256, SMEM128>>>(a, a, M/128, nullptr, nullptr, nullptr);
    }
    {
        GArgs a{y1, NH, wtb + W_ENC2, enc_b2, ctx, 512, NH};
        gemm_bf<128,0,1,0,0><<<dim3(NL/128, M/128), 256, SMEM128>>>(a, a, M/128, nullptr, nullptr, nullptr);
    }

    // ---- fctx ----
    {
        GArgs a{ctx, 512, wtb + W_F1C, f_b1, fctx, NH, 512};
        gemm_bf<128,0,0,0,1><<<dim3(NH/128, M/128), 256, SMEM128>>>(a, a, M/128, nullptr, nullptr, nullptr);
    }

    // ---- q ----
    {
        GArgs a{ctx, NT * 512, wtb + W_QZ0, qz0_b, q, 512, 512};
        gemm_bf<128,0,0,0,0><<<dim3(512/128, NB/128), 256, SMEM128>>>(a, a, NB/128, nullptr, nullptr, nullptr);
    }

    // ---- persistent scan ----
    scan_k<<<128, 256, SMEMP>>>(ts, noise, z, zs, hf, hh,
                                wtb + W_F1Z, wtb + W_H1, wtb + W_F2, wtb + W_H2,
                                h_b1, f_b2, h_b2, fctx, gamma, dkl8,
                                flagA, flagB, flagP, pb,
                                q, eps0, pz0_mean, pz0_logstd, kl0);

    // ---- decoder fused with NLL reduction ----
    {
        GArgs a{zs, NL, wtb + W_PROJ, proj_b, nullptr, ND, NL};
        gemm_bf<128,0,0,1,0><<<dim3(ND/128, M/128), 256, SMEM128>>>(a, zg, M/128, xs, noise_std, partials);
    }

    // ---- finalize ----
    finalize_k<<<1, 256>>>(partials, (M/128) * (ND/128), dkl8, kl0, noise_std, (float*)d_out);

    (void)in_sizes; (void)n_in; (void)out_size;
}